// round 15
// baseline (speedup 1.0000x reference)
#include <cuda_runtime.h>
#include <cuda_bf16.h>
#include <cstdint>

#define NPOS 2304          // 48*48
#define PPAD 2916          // 54*54
typedef unsigned long long ull;

// Scratch (device globals; no runtime allocation)
__device__ float Qbuf[2 * 4 * 2304 * 64];   // [b][g][p][c64]
__device__ float Kbuf[2 * 8 * 2916 * 32];   // [b][SL][padded pos][c32]
__device__ float Vbuf[2 * 4 * 2916 * 64];   // [b][g][padded pos][c64]

// ---------------------------------------------------------------------------
// helpers
// ---------------------------------------------------------------------------
__device__ __forceinline__ ull dup2(float a) {
    ull r; asm("mov.b64 %0, {%1, %1};" : "=l"(r) : "f"(a)); return r;
}
__device__ __forceinline__ void fma2(ull& d, ull a, ull b) {
    asm("fma.rn.f32x2 %0, %1, %2, %0;" : "+l"(d) : "l"(a), "l"(b));
}
__device__ __forceinline__ ull add2(ull a, ull b) {
    ull r; asm("add.rn.f32x2 %0, %1, %2;" : "=l"(r) : "l"(a), "l"(b)); return r;
}
__device__ __forceinline__ uint32_t smem_u32(const void* p) {
    uint32_t a;
    asm("{ .reg .u64 t; cvta.to.shared.u64 t, %1; cvt.u32.u64 %0, t; }" : "=r"(a) : "l"(p));
    return a;
}

// Truncation-based fp32 -> bf16 hi/lo split for a float4 (12 ops vs 18).
// hi = mantissa-truncated bf16 (exact); lo = rn(x - hi), residual ~2^-17.
__device__ __forceinline__ void split4(float4 v, uint2& hi, uint2& lo) {
    uint32_t bx = __float_as_uint(v.x), by = __float_as_uint(v.y);
    uint32_t bz = __float_as_uint(v.z), bw = __float_as_uint(v.w);
    uint32_t hxy, hzw;
    asm("prmt.b32 %0, %1, %2, 0x7632;" : "=r"(hxy) : "r"(bx), "r"(by));
    asm("prmt.b32 %0, %1, %2, 0x7632;" : "=r"(hzw) : "r"(bz), "r"(bw));
    float lx = v.x - __uint_as_float(bx & 0xFFFF0000u);
    float ly = v.y - __uint_as_float(by & 0xFFFF0000u);
    float lz = v.z - __uint_as_float(bz & 0xFFFF0000u);
    float lw = v.w - __uint_as_float(bw & 0xFFFF0000u);
    uint32_t lxy, lzw;
    asm("cvt.rn.bf16x2.f32 %0, %1, %2;" : "=r"(lxy) : "f"(ly), "f"(lx));
    asm("cvt.rn.bf16x2.f32 %0, %1, %2;" : "=r"(lzw) : "f"(lw), "f"(lz));
    hi = make_uint2(hxy, hzw);
    lo = make_uint2(lxy, lzw);
}

#define LDSM4(R, addr) \
    asm volatile("ldmatrix.sync.aligned.m8n8.x4.shared.b16 {%0,%1,%2,%3}, [%4];" \
                 : "=r"((R)[0]), "=r"((R)[1]), "=r"((R)[2]), "=r"((R)[3]) : "r"(addr))

#define MMA16816(D, A, B0, B1) \
    asm volatile("mma.sync.aligned.m16n8k16.row.col.f32.bf16.bf16.f32 " \
                 "{%0,%1,%2,%3}, {%4,%5,%6,%7}, {%8,%9}, {%0,%1,%2,%3};" \
                 : "+f"((D)[0]), "+f"((D)[1]), "+f"((D)[2]), "+f"((D)[3]) \
                 : "r"((A)[0]), "r"((A)[1]), "r"((A)[2]), "r"((A)[3]), "r"(B0), "r"(B1))

// ---------------------------------------------------------------------------
// Kernel 1: conv GEMM on HMMA (truncation bf16 split), tile 128(o) x 96(n).
// 288 CTAs = 0.97 waves at 2 CTAs/SM. 8 warps = 4(o) x 2(n), warp 32x48.
// ---------------------------------------------------------------------------
#define AHI_OFF 0
#define ALO_OFF 32768
#define BHI_OFF 65536
#define BLO_OFF 90112
#define CONV_SMEM 114688

__global__ __launch_bounds__(256, 2) void conv_mma(const float* __restrict__ x,
                                                   const float* __restrict__ w) {
    extern __shared__ char cm[];
    const uint32_t sb = smem_u32(cm);
    const int b  = blockIdx.z;
    const int o0 = blockIdx.y * 128;
    const int n0 = blockIdx.x * 96;
    const int t  = threadIdx.x;
    const int lane = t & 31, wid = t >> 5;
    const float* Xb = x + b * (256 * NPOS);

    float d[2][6][4];
#pragma unroll
    for (int i = 0; i < 2; i++)
#pragma unroll
        for (int j = 0; j < 6; j++)
#pragma unroll
            for (int k = 0; k < 4; k++) d[i][j][k] = 0.f;

    const int wo = wid & 3;       // o warp tile (32 rows)
    const int wn = wid >> 2;      // n warp tile (48 cols)

    const int lrA = (lane & 7) + (((lane >> 3) & 1) << 3);
    const int caA = ((lane >> 4) & 1) * 16;
    const int lrB = (lane & 7) + (((lane >> 4) & 1) << 3);
    const int caB = ((lane >> 3) & 1) * 16;

#pragma unroll 1
    for (int ch = 0; ch < 2; ch++) {
        const int c0 = ch * 128;
        __syncthreads();

        // ---- stage A = W[o0..+127][c0..+127] as bf16 hi/lo ----
#pragma unroll
        for (int r = 0; r < 16; r++) {
            int fid = t + 256 * r;
            int row = fid >> 5, c4 = fid & 31;
            float4 v = *(const float4*)(w + (o0 + row) * 256 + c0 + c4 * 4);
            uint2 hi, lo;
            split4(v, hi, lo);
            uint32_t addr = row * 256 + ((c4 * 8) ^ ((row & 7) << 4));
            *(uint2*)(cm + AHI_OFF + addr) = hi;
            *(uint2*)(cm + ALO_OFF + addr) = lo;
        }
        // ---- stage B = X[c0..+127][n0..+95] transposed to [n][k] ----
        {
            const int tn = t & 31, tk = t >> 5;   // tk 0..7
#pragma unroll
            for (int q = 0; q < 12; q++) {
                int ng = q % 3, kg = q / 3;       // kg 0..3
                int n = ng * 32 + tn;             // 0..95
                int k4 = kg * 8 + tk;             // 0..31
                const float* p = Xb + (c0 + k4 * 4) * NPOS + n0 + n;
                float4 v = make_float4(p[0], p[NPOS], p[2 * NPOS], p[3 * NPOS]);
                uint2 hi, lo;
                split4(v, hi, lo);
                uint32_t addr = n * 256 + ((k4 * 8) ^ ((n & 7) << 4));
                *(uint2*)(cm + BHI_OFF + addr) = hi;
                *(uint2*)(cm + BLO_OFF + addr) = lo;
            }
        }
        __syncthreads();

        // ---- MMA: 8 k-steps of 16 ----
#pragma unroll
        for (int ks = 0; ks < 8; ks++) {
            const int kb = ks * 32;
            uint32_t ahi[2][4], alo[2][4], bhi[3][4], blo[3][4];
#pragma unroll
            for (int mt = 0; mt < 2; mt++) {
                int orow = wo * 32 + mt * 16 + lrA;
                uint32_t off = orow * 256 + ((kb + caA) ^ ((orow & 7) << 4));
                LDSM4(ahi[mt], sb + AHI_OFF + off);
                LDSM4(alo[mt], sb + ALO_OFF + off);
            }
#pragma unroll
            for (int np = 0; np < 3; np++) {
                int nrow = wn * 48 + np * 16 + lrB;
                uint32_t off = nrow * 256 + ((kb + caB) ^ ((nrow & 7) << 4));
                LDSM4(bhi[np], sb + BHI_OFF + off);
                LDSM4(blo[np], sb + BLO_OFF + off);
            }
#pragma unroll
            for (int mt = 0; mt < 2; mt++)
#pragma unroll
                for (int nt = 0; nt < 6; nt++) {
                    const int np = nt >> 1, h = nt & 1;
                    MMA16816(d[mt][nt], ahi[mt], bhi[np][2 * h], bhi[np][2 * h + 1]);
                    MMA16816(d[mt][nt], ahi[mt], blo[np][2 * h], blo[np][2 * h + 1]);
                    MMA16816(d[mt][nt], alo[mt], bhi[np][2 * h], bhi[np][2 * h + 1]);
                }
        }
    }

    // ---- epilogue: transpose through smem, then float4 scatter ----
    __syncthreads();
    float* C = (float*)cm;   // [96 n][132 o]
    const int gid = lane >> 2, tig = lane & 3;
#pragma unroll
    for (int mt = 0; mt < 2; mt++)
#pragma unroll
        for (int nt = 0; nt < 6; nt++) {
            int o_l = wo * 32 + mt * 16 + gid;
            int n_l = wn * 48 + nt * 8 + tig * 2;
            C[n_l * 132 + o_l]           = d[mt][nt][0];
            C[(n_l + 1) * 132 + o_l]     = d[mt][nt][1];
            C[n_l * 132 + o_l + 8]       = d[mt][nt][2];
            C[(n_l + 1) * 132 + o_l + 8] = d[mt][nt][3];
        }
    __syncthreads();

    {
#pragma unroll
        for (int q = 0; q < 12; q++) {
            int fid = t + 256 * q;           // 0..3071
            int n = fid >> 5;                // 0..95
            int o4 = fid & 31;               // 0..31
            const int hw = n0 + n;
            unsigned uhw = (unsigned)hw;
            int i2 = uhw / 48u, j2 = uhw - 48u * i2;
            int pp = (i2 + 3) * 54 + (j2 + 3);
            float4 v = *(float4*)&C[n * 132 + o4 * 4];
            int o = o0 + o4 * 4;
            if (o < 256) {
                int g = o >> 6;
                *(float4*)&Qbuf[(((b * 4 + g) * 2304 + hw) << 6) + (o & 63)] = v;
            } else if (o < 512) {
                int ok = o - 256;
                int SL = ((ok >> 5) & 1) * 4 + (ok >> 6);
                *(float4*)&Kbuf[(((b * 8 + SL) * PPAD + pp) << 5) + (ok & 31)] = v;
            } else {
                int ov = o - 512;
                *(float4*)&Vbuf[(((b * 4 + (ov >> 6)) * PPAD + pp) << 6) + (ov & 63)] = v;
            }
        }
    }
}

// ---------------------------------------------------------------------------
// Kernel 2: attention (batched transpose-reduce QK; AV unpredicated via
// zero-padded atts slots 49..51; 2 rows/block, 768 threads).
// ---------------------------------------------------------------------------
__device__ __forceinline__ float red8(float v) {
    v += __shfl_xor_sync(0xffffffffu, v, 1);
    v += __shfl_xor_sync(0xffffffffu, v, 2);
    v += __shfl_xor_sync(0xffffffffu, v, 4);
    return v;
}
__device__ __forceinline__ float max8(float v) {
    v = fmaxf(v, __shfl_xor_sync(0xffffffffu, v, 1));
    v = fmaxf(v, __shfl_xor_sync(0xffffffffu, v, 2));
    v = fmaxf(v, __shfl_xor_sync(0xffffffffu, v, 4));
    return v;
}
__device__ __forceinline__ float dot4(float4 a, float4 b) {
    return a.x * b.x + a.y * b.y + a.z * b.z + a.w * b.w;
}

#define KT_F4 4320    // 10*54*8
#define VT_F4 6912    // 8*54*16
#define ATT_STRIDE 52
// floats: Kt 17280 + Vt 27648 + atts 4992 + rtab 1536
#define ATT_TAIL_FLOATS (96 * ATT_STRIDE + 96 * 16)

__global__ __launch_bounds__(768, 1) void attn_kernel(const float* __restrict__ rpeh,
                                                      const float* __restrict__ rpew,
                                                      float* __restrict__ out) {
    extern __shared__ float sm[];
    float* Kt   = sm;                        // 17280 floats
    float* Vt   = sm + 17280;                // 27648 floats
    float* atts = Vt + 27648;                // 96*52
    float* rtab = atts + 96 * ATT_STRIDE;    // 96*16

    const int ip0 = blockIdx.x * 2;
    const int g   = blockIdx.y;
    const int b   = blockIdx.z;
    const int t   = threadIdx.x;

    const int s_  = (ip0 >= 24) ? 1 : 0;
    const int SL  = 2 * g + s_;
    const int R0  = 2 * ip0 - 48 * s_;

    const float4 z4 = make_float4(0.f, 0.f, 0.f, 0.f);

    {
        const float4* ks = (const float4*)(Kbuf + (((b * 8 + SL) * PPAD + R0 * 54) << 5));
        float4* kt4s = (float4*)Kt;
        for (int i = t; i < KT_F4; i += 768) {
            unsigned pl = (unsigned)(i >> 3);
            unsigned lr = pl / 54u, col = pl - 54u * lr;
            unsigned grow = (unsigned)R0 + lr;
            bool inter = (grow - 3u) < 48u && (col - 3u) < 48u;
            kt4s[i] = inter ? ks[i] : z4;
        }
        const float4* vsrc = (const float4*)(Vbuf + (((b * 4 + g) * PPAD + ip0 * 54) << 6));
        float4* vt4s = (float4*)Vt;
        for (int i = t; i < VT_F4; i += 768) {
            unsigned pl = (unsigned)(i >> 4);
            unsigned lr = pl / 54u, col = pl - 54u * lr;
            unsigned grow = (unsigned)ip0 + lr;
            bool inter = (grow - 3u) < 48u && (col - 3u) < 48u;
            vt4s[i] = inter ? vsrc[i] : z4;
        }
        // zero atts + rtab (covers pad slots k=49..51 and unused rtab slots)
        float4* tail4 = (float4*)atts;
        for (int i = t; i < ATT_TAIL_FLOATS / 4; i += 768) tail4[i] = z4;
    }

    const int rh  = (t >= 384) ? 1 : 0;
    const int tt  = t - rh * 384;
    const int ip  = ip0 + rh;
    const int pos = tt >> 3;
    const int sub = tt & 7;
    const int pidx = rh * 48 + pos;

    const float* qp = Qbuf + (((b * 4 + g) * 2304 + ip * 48 + pos) << 6);
    const float4 qlo = *(const float4*)(qp + 4 * sub);
    const float4 qhi = *(const float4*)(qp + 32 + 4 * sub);
    const ull ql0 = *(const ull*)&qlo.x, ql1 = *(const ull*)&qlo.z;
    const ull qh0 = *(const ull*)&qhi.x, qh1 = *(const ull*)&qhi.z;

    const bool useH = (SL < 4);
    const float* rp = useH ? (rpeh + SL * 224) : (rpew + (SL - 4) * 224);
    __syncthreads();   // zero-fill + staging visible before rtab writes
    {
        float Rlo[7], Rhi[7];
#pragma unroll
        for (int tq = 0; tq < 7; tq++) {
            float4 rv = *(const float4*)(rp + tq * 32 + 4 * sub);
            Rlo[tq] = red8(dot4(qlo, rv));
            Rhi[tq] = red8(dot4(qhi, rv));
        }
        if (sub == 0) {
#pragma unroll
            for (int tq = 0; tq < 7; tq++) {
                rtab[pidx * 16 + tq]     = Rlo[tq];
                rtab[pidx * 16 + 8 + tq] = Rhi[tq];
            }
        }
    }

    __syncthreads();

    float Radd[7];
#pragma unroll
    for (int i = 0; i < 7; i++) {
        int k = 8 * i + sub;
        int kc = (k > 48) ? 48 : k;
        int wA, wB;
        if (kc < 24)       { wA = 2 * kc;      wB = 2 * kc + 1; }
        else if (kc == 24) { wA = 48;          wB = 0; }
        else               { wA = 2 * kc - 49; wB = 2 * kc - 48; }
        int khA = wA / 7, kwA = wA - 7 * khA;
        int khB = wB / 7, kwB = wB - 7 * khB;
        int idxA = useH ? khA : kwA;
        int idxB = useH ? khB : kwB;
        Radd[i] = rtab[pidx * 16 + idxA] + rtab[pidx * 16 + 8 + idxB];
    }

    const int rsel = (pos >= 24) ? 1 : 0;
    const int j0 = 2 * pos - 48 * rsel;
    const int krow0 = 2 * rh + rsel;

    const float4* kt4 = (const float4*)Kt;
    const float4* kbase = kt4 + ((krow0 * 54 + j0) << 3) + sub;

    float Lreg[7];
#pragma unroll
    for (int c = 0; c < 7; c++) {
        float P[8];
#pragma unroll
        for (int kk = 0; kk < 8; kk++) {
            const int k = 8 * c + kk;
            const int kc = (k > 48) ? 48 : k;
            int wA, wB, rA, rB;
            if (kc < 24)       { wA = 2 * kc;      rA = 0; wB = 2 * kc + 1;  rB = 0; }
            else if (kc == 24) { wA = 48;          rA = 0; wB = 0;           rB = 1; }
            else               { wA = 2 * kc - 49; rA = 1; wB = 2 * kc - 48; rB = 1; }
            const int khA = wA / 7, kwA = wA % 7;
            const int khB = wB / 7, kwB = wB % 7;
            float4 va = kbase[(khA * 54 + rA + kwA) << 3];
            float4 vb = kbase[(khB * 54 + rB + kwB) << 3];
            ull aA = 0ull, aB = 0ull;
            fma2(aA, *(const ull*)&va.x, ql0);
            fma2(aA, *(const ull*)&va.z, ql1);
            fma2(aB, *(const ull*)&vb.x, qh0);
            fma2(aB, *(const ull*)&vb.z, qh1);
            ull s = add2(aA, aB);
            float2 sf = *(float2*)&s;
            P[kk] = sf.x + sf.y;
        }
        {
            const bool h4 = (sub & 4);
            float t0 = h4 ? P[0] : P[4];
            float t1 = h4 ? P[1] : P[5];
            float t2 = h4 ? P[2] : P[6];
            float t3 = h4 ? P[3] : P[7];
            float r0 = __shfl_xor_sync(0xffffffffu, t0, 4);
            float r1 = __shfl_xor_sync(0xffffffffu, t1, 4);
            float r2 = __shfl_xor_sync(0xffffffffu, t2, 4);
            float r3 = __shfl_xor_sync(0xffffffffu, t3, 4);
            float q0 = (h4 ? P[4] : P[0]) + r0;
            float q1 = (h4 ? P[5] : P[1]) + r1;
            float q2 = (h4 ? P[6] : P[2]) + r2;
            float q3 = (h4 ? P[7] : P[3]) + r3;

            const bool h2 = (sub & 2);
            float u0 = h2 ? q0 : q2;
            float u1 = h2 ? q1 : q3;
            float s0 = __shfl_xor_sync(0xffffffffu, u0, 2);
            float s1 = __shfl_xor_sync(0xffffffffu, u1, 2);
            float w0 = (h2 ? q2 : q0) + s0;
            float w1 = (h2 ? q3 : q1) + s1;

            const bool h1 = (sub & 1);
            float z0 = h1 ? w0 : w1;
            float z1 = __shfl_xor_sync(0xffffffffu, z0, 1);
            float fin = (h1 ? w1 : w0) + z1;
            Lreg[c] = fin + Radd[c];
        }
    }
    if (sub != 0) Lreg[6] = -1e30f;

    const int nk = (sub == 0) ? 7 : 6;
    float m = -1e30f;
#pragma unroll
    for (int i = 0; i < 7; i++)
        if (i < nk) m = fmaxf(m, Lreg[i]);
    m = max8(m);
    float ssum = 0.f;
#pragma unroll
    for (int i = 0; i < 7; i++)
        if (i < nk) { Lreg[i] = __expf(Lreg[i] - m); ssum += Lreg[i]; }
    ssum = red8(ssum);
    float inv = 1.0f / ssum;
#pragma unroll
    for (int i = 0; i < 7; i++) {
        int k = 8 * i + sub;
        if (k < 49) atts[pidx * ATT_STRIDE + k] = Lreg[i] * inv;
        // slots 49..51 remain 0 from the zero-init
    }
    __syncwarp();

    // AV (f32x2), atts as float4, unpredicated over 52 slots (49..51 are 0;
    // their V reads land in zero/finite smem and contribute exactly 0)
    ull a0[2] = {0ull, 0ull}, a1[2] = {0ull, 0ull};
    const float4* vt4 = (const float4*)Vt;
#pragma unroll
    for (int kq = 0; kq < 13; kq++) {
        float4 a4 = *(const float4*)&atts[pidx * ATT_STRIDE + kq * 4];
        float aa[4] = {a4.x, a4.y, a4.z, a4.w};
#pragma unroll
        for (int j = 0; j < 4; j++) {
            const int k = kq * 4 + j;
            const int kh = k / 7, kw = k % 7;
            ull ad = dup2(aa[j]);
            const float4* vv = vt4 + ((((rh + kh) * 54 + pos + kw) << 4) + sub);
            float4 v0 = vv[0];
            float4 v1 = vv[8];
            fma2(a0[0], ad, *(ull*)&v0.x);
            fma2(a0[1], ad, *(ull*)&v0.z);
            fma2(a1[0], ad, *(ull*)&v1.x);
            fma2(a1[1], ad, *(ull*)&v1.z);
        }
    }
    float4 acc0 = *(float4*)&a0[0];
    float4 acc1 = *(float4*)&a1[0];

    float* op = out + (b * 256 + g * 64) * NPOS + ip * 48 + pos;
    op[(4 * sub + 0) * NPOS] = acc0.x;
    op[(4 * sub + 1) * NPOS] = acc0.y;
    op[(4 * sub + 2) * NPOS] = acc0.z;
    op[(4 * sub + 3) * NPOS] = acc0.w;
    op[(32 + 4 * sub + 0) * NPOS] = acc1.x;
    op[(32 + 4 * sub + 1) * NPOS] = acc1.y;
    op[(32 + 4 * sub + 2) * NPOS] = acc1.z;
    op[(32 + 4 * sub + 3) * NPOS] = acc1.w;
}

// ---------------------------------------------------------------------------
extern "C" void kernel_launch(void* const* d_in, const int* in_sizes, int n_in,
                              void* d_out, int out_size) {
    const float* x  = (const float*)d_in[0];
    const float* w  = (const float*)d_in[1];
    const float* rh = (const float*)d_in[2];
    const float* rw = (const float*)d_in[3];
    float* out = (float*)d_out;

    cudaFuncSetAttribute(conv_mma, cudaFuncAttributeMaxDynamicSharedMemorySize, CONV_SMEM);
    dim3 gc(24, 6, 2);   // n=2304/96, o=768/128, b
    conv_mma<<<gc, 256, CONV_SMEM>>>(x, w);

    const int SMEM = (17280 + 27648 + ATT_TAIL_FLOATS) * 4;
    cudaFuncSetAttribute(attn_kernel, cudaFuncAttributeMaxDynamicSharedMemorySize, SMEM);
    dim3 ga(24, 4, 2);
    attn_kernel<<<ga, 768, SMEM>>>(rh, rw, out);
}

// round 16
// speedup vs baseline: 1.0179x; 1.0179x over previous
#include <cuda_runtime.h>
#include <cuda_bf16.h>
#include <cstdint>

#define NPOS 2304          // 48*48
#define PPAD 2916          // 54*54
typedef unsigned long long ull;

// Scratch (device globals; no runtime allocation)
__device__ float Qbuf[2 * 4 * 2304 * 64];   // [b][g][p][c64]
__device__ float Kbuf[2 * 8 * 2916 * 32];   // [b][SL][padded pos][c32]
__device__ float Vbuf[2 * 4 * 2916 * 64];   // [b][g][padded pos][c64]

// ---------------------------------------------------------------------------
// helpers
// ---------------------------------------------------------------------------
__device__ __forceinline__ ull dup2(float a) {
    ull r; asm("mov.b64 %0, {%1, %1};" : "=l"(r) : "f"(a)); return r;
}
__device__ __forceinline__ void fma2(ull& d, ull a, ull b) {
    asm("fma.rn.f32x2 %0, %1, %2, %0;" : "+l"(d) : "l"(a), "l"(b));
}
__device__ __forceinline__ ull add2(ull a, ull b) {
    ull r; asm("add.rn.f32x2 %0, %1, %2;" : "=l"(r) : "l"(a), "l"(b)); return r;
}
__device__ __forceinline__ uint32_t smem_u32(const void* p) {
    uint32_t a;
    asm("{ .reg .u64 t; cvta.to.shared.u64 t, %1; cvt.u32.u64 %0, t; }" : "=r"(a) : "l"(p));
    return a;
}

// Truncation-based fp32 -> bf16 hi/lo split for a float4 (12 ops vs 18).
__device__ __forceinline__ void split4(float4 v, uint2& hi, uint2& lo) {
    uint32_t bx = __float_as_uint(v.x), by = __float_as_uint(v.y);
    uint32_t bz = __float_as_uint(v.z), bw = __float_as_uint(v.w);
    uint32_t hxy, hzw;
    asm("prmt.b32 %0, %1, %2, 0x7632;" : "=r"(hxy) : "r"(bx), "r"(by));
    asm("prmt.b32 %0, %1, %2, 0x7632;" : "=r"(hzw) : "r"(bz), "r"(bw));
    float lx = v.x - __uint_as_float(bx & 0xFFFF0000u);
    float ly = v.y - __uint_as_float(by & 0xFFFF0000u);
    float lz = v.z - __uint_as_float(bz & 0xFFFF0000u);
    float lw = v.w - __uint_as_float(bw & 0xFFFF0000u);
    uint32_t lxy, lzw;
    asm("cvt.rn.bf16x2.f32 %0, %1, %2;" : "=r"(lxy) : "f"(ly), "f"(lx));
    asm("cvt.rn.bf16x2.f32 %0, %1, %2;" : "=r"(lzw) : "f"(lw), "f"(lz));
    hi = make_uint2(hxy, hzw);
    lo = make_uint2(lxy, lzw);
}

#define LDSM4(R, addr) \
    asm volatile("ldmatrix.sync.aligned.m8n8.x4.shared.b16 {%0,%1,%2,%3}, [%4];" \
                 : "=r"((R)[0]), "=r"((R)[1]), "=r"((R)[2]), "=r"((R)[3]) : "r"(addr))

#define MMA16816(D, A, B0, B1) \
    asm volatile("mma.sync.aligned.m16n8k16.row.col.f32.bf16.bf16.f32 " \
                 "{%0,%1,%2,%3}, {%4,%5,%6,%7}, {%8,%9}, {%0,%1,%2,%3};" \
                 : "+f"((D)[0]), "+f"((D)[1]), "+f"((D)[2]), "+f"((D)[3]) \
                 : "r"((A)[0]), "r"((A)[1]), "r"((A)[2]), "r"((A)[3]), "r"(B0), "r"(B1))

// ---------------------------------------------------------------------------
// Kernel 1: conv GEMM on HMMA (truncation bf16 split), tile 128(o) x 96(n).
// 288 CTAs = 0.97 waves at 2 CTAs/SM. 8 warps = 4(o) x 2(n), warp 32x48.
// ---------------------------------------------------------------------------
#define AHI_OFF 0
#define ALO_OFF 32768
#define BHI_OFF 65536
#define BLO_OFF 90112
#define CONV_SMEM 114688

__global__ __launch_bounds__(256, 2) void conv_mma(const float* __restrict__ x,
                                                   const float* __restrict__ w) {
    extern __shared__ char cm[];
    const uint32_t sb = smem_u32(cm);
    const int b  = blockIdx.z;
    const int o0 = blockIdx.y * 128;
    const int n0 = blockIdx.x * 96;
    const int t  = threadIdx.x;
    const int lane = t & 31, wid = t >> 5;
    const float* Xb = x + b * (256 * NPOS);

    float d[2][6][4];
#pragma unroll
    for (int i = 0; i < 2; i++)
#pragma unroll
        for (int j = 0; j < 6; j++)
#pragma unroll
            for (int k = 0; k < 4; k++) d[i][j][k] = 0.f;

    const int wo = wid & 3;
    const int wn = wid >> 2;

    const int lrA = (lane & 7) + (((lane >> 3) & 1) << 3);
    const int caA = ((lane >> 4) & 1) * 16;
    const int lrB = (lane & 7) + (((lane >> 4) & 1) << 3);
    const int caB = ((lane >> 3) & 1) * 16;

#pragma unroll 1
    for (int ch = 0; ch < 2; ch++) {
        const int c0 = ch * 128;
        __syncthreads();

        // ---- stage A = W[o0..+127][c0..+127] as bf16 hi/lo ----
#pragma unroll
        for (int r = 0; r < 16; r++) {
            int fid = t + 256 * r;
            int row = fid >> 5, c4 = fid & 31;
            float4 v = *(const float4*)(w + (o0 + row) * 256 + c0 + c4 * 4);
            uint2 hi, lo;
            split4(v, hi, lo);
            uint32_t addr = row * 256 + ((c4 * 8) ^ ((row & 7) << 4));
            *(uint2*)(cm + AHI_OFF + addr) = hi;
            *(uint2*)(cm + ALO_OFF + addr) = lo;
        }
        // ---- stage B = X[c0..+127][n0..+95] transposed to [n][k] ----
        {
            const int tn = t & 31, tk = t >> 5;
#pragma unroll
            for (int q = 0; q < 12; q++) {
                int ng = q % 3, kg = q / 3;
                int n = ng * 32 + tn;
                int k4 = kg * 8 + tk;
                const float* p = Xb + (c0 + k4 * 4) * NPOS + n0 + n;
                float4 v = make_float4(p[0], p[NPOS], p[2 * NPOS], p[3 * NPOS]);
                uint2 hi, lo;
                split4(v, hi, lo);
                uint32_t addr = n * 256 + ((k4 * 8) ^ ((n & 7) << 4));
                *(uint2*)(cm + BHI_OFF + addr) = hi;
                *(uint2*)(cm + BLO_OFF + addr) = lo;
            }
        }
        __syncthreads();

        // ---- MMA: 8 k-steps of 16 ----
#pragma unroll
        for (int ks = 0; ks < 8; ks++) {
            const int kb = ks * 32;
            uint32_t ahi[2][4], alo[2][4], bhi[3][4], blo[3][4];
#pragma unroll
            for (int mt = 0; mt < 2; mt++) {
                int orow = wo * 32 + mt * 16 + lrA;
                uint32_t off = orow * 256 + ((kb + caA) ^ ((orow & 7) << 4));
                LDSM4(ahi[mt], sb + AHI_OFF + off);
                LDSM4(alo[mt], sb + ALO_OFF + off);
            }
#pragma unroll
            for (int np = 0; np < 3; np++) {
                int nrow = wn * 48 + np * 16 + lrB;
                uint32_t off = nrow * 256 + ((kb + caB) ^ ((nrow & 7) << 4));
                LDSM4(bhi[np], sb + BHI_OFF + off);
                LDSM4(blo[np], sb + BLO_OFF + off);
            }
#pragma unroll
            for (int mt = 0; mt < 2; mt++)
#pragma unroll
                for (int nt = 0; nt < 6; nt++) {
                    const int np = nt >> 1, h = nt & 1;
                    MMA16816(d[mt][nt], ahi[mt], bhi[np][2 * h], bhi[np][2 * h + 1]);
                    MMA16816(d[mt][nt], ahi[mt], blo[np][2 * h], blo[np][2 * h + 1]);
                    MMA16816(d[mt][nt], alo[mt], bhi[np][2 * h], bhi[np][2 * h + 1]);
                }
        }
    }

    // ---- epilogue: transpose through smem, then float4 scatter ----
    __syncthreads();
    float* C = (float*)cm;   // [96 n][132 o]
    const int gid = lane >> 2, tig = lane & 3;
#pragma unroll
    for (int mt = 0; mt < 2; mt++)
#pragma unroll
        for (int nt = 0; nt < 6; nt++) {
            int o_l = wo * 32 + mt * 16 + gid;
            int n_l = wn * 48 + nt * 8 + tig * 2;
            C[n_l * 132 + o_l]           = d[mt][nt][0];
            C[(n_l + 1) * 132 + o_l]     = d[mt][nt][1];
            C[n_l * 132 + o_l + 8]       = d[mt][nt][2];
            C[(n_l + 1) * 132 + o_l + 8] = d[mt][nt][3];
        }
    __syncthreads();

    {
#pragma unroll
        for (int q = 0; q < 12; q++) {
            int fid = t + 256 * q;
            int n = fid >> 5;
            int o4 = fid & 31;
            const int hw = n0 + n;
            unsigned uhw = (unsigned)hw;
            int i2 = uhw / 48u, j2 = uhw - 48u * i2;
            int pp = (i2 + 3) * 54 + (j2 + 3);
            float4 v = *(float4*)&C[n * 132 + o4 * 4];
            int o = o0 + o4 * 4;
            if (o < 256) {
                int g = o >> 6;
                *(float4*)&Qbuf[(((b * 4 + g) * 2304 + hw) << 6) + (o & 63)] = v;
            } else if (o < 512) {
                int ok = o - 256;
                int SL = ((ok >> 5) & 1) * 4 + (ok >> 6);
                *(float4*)&Kbuf[(((b * 8 + SL) * PPAD + pp) << 5) + (ok & 31)] = v;
            } else {
                int ov = o - 512;
                *(float4*)&Vbuf[(((b * 4 + (ov >> 6)) * PPAD + pp) << 6) + (ov & 63)] = v;
            }
        }
    }
}

// ---------------------------------------------------------------------------
// Kernel 2: attention (R14 structure; RPE now uses batched transpose-reduce).
// ---------------------------------------------------------------------------
__device__ __forceinline__ float red8(float v) {
    v += __shfl_xor_sync(0xffffffffu, v, 1);
    v += __shfl_xor_sync(0xffffffffu, v, 2);
    v += __shfl_xor_sync(0xffffffffu, v, 4);
    return v;
}
__device__ __forceinline__ float max8(float v) {
    v = fmaxf(v, __shfl_xor_sync(0xffffffffu, v, 1));
    v = fmaxf(v, __shfl_xor_sync(0xffffffffu, v, 2));
    v = fmaxf(v, __shfl_xor_sync(0xffffffffu, v, 4));
    return v;
}
__device__ __forceinline__ float dot4(float4 a, float4 b) {
    return a.x * b.x + a.y * b.y + a.z * b.z + a.w * b.w;
}

// 8x8 transpose-reduce across an 8-lane group: lane `sub` returns sum over
// the group's lanes of P[sub]. 7 shuffles, no serial red8 chains.
__device__ __forceinline__ float treduce8(const float P[8], int sub) {
    const bool h4 = (sub & 4);
    float t0 = h4 ? P[0] : P[4];
    float t1 = h4 ? P[1] : P[5];
    float t2 = h4 ? P[2] : P[6];
    float t3 = h4 ? P[3] : P[7];
    float r0 = __shfl_xor_sync(0xffffffffu, t0, 4);
    float r1 = __shfl_xor_sync(0xffffffffu, t1, 4);
    float r2 = __shfl_xor_sync(0xffffffffu, t2, 4);
    float r3 = __shfl_xor_sync(0xffffffffu, t3, 4);
    float q0 = (h4 ? P[4] : P[0]) + r0;
    float q1 = (h4 ? P[5] : P[1]) + r1;
    float q2 = (h4 ? P[6] : P[2]) + r2;
    float q3 = (h4 ? P[7] : P[3]) + r3;
    const bool h2 = (sub & 2);
    float u0 = h2 ? q0 : q2;
    float u1 = h2 ? q1 : q3;
    float s0 = __shfl_xor_sync(0xffffffffu, u0, 2);
    float s1 = __shfl_xor_sync(0xffffffffu, u1, 2);
    float w0 = (h2 ? q2 : q0) + s0;
    float w1 = (h2 ? q3 : q1) + s1;
    const bool h1 = (sub & 1);
    float z0 = h1 ? w0 : w1;
    float z1 = __shfl_xor_sync(0xffffffffu, z0, 1);
    return (h1 ? w1 : w0) + z1;
}

#define KT_F4 4320    // 10*54*8
#define VT_F4 6912    // 8*54*16
#define ATT_STRIDE 52

__global__ __launch_bounds__(768, 1) void attn_kernel(const float* __restrict__ rpeh,
                                                      const float* __restrict__ rpew,
                                                      float* __restrict__ out) {
    extern __shared__ float sm[];
    float* Kt   = sm;                        // 17280 floats
    float* Vt   = sm + 17280;                // 27648 floats
    float* atts = Vt + 27648;                // 96*52
    float* rtab = atts + 96 * ATT_STRIDE;    // 96*16

    const int ip0 = blockIdx.x * 2;
    const int g   = blockIdx.y;
    const int b   = blockIdx.z;
    const int t   = threadIdx.x;

    const int s_  = (ip0 >= 24) ? 1 : 0;
    const int SL  = 2 * g + s_;
    const int R0  = 2 * ip0 - 48 * s_;

    const float4 z4 = make_float4(0.f, 0.f, 0.f, 0.f);

    {
        const float4* ks = (const float4*)(Kbuf + (((b * 8 + SL) * PPAD + R0 * 54) << 5));
        float4* kt4s = (float4*)Kt;
        for (int i = t; i < KT_F4; i += 768) {
            unsigned pl = (unsigned)(i >> 3);
            unsigned lr = pl / 54u, col = pl - 54u * lr;
            unsigned grow = (unsigned)R0 + lr;
            bool inter = (grow - 3u) < 48u && (col - 3u) < 48u;
            kt4s[i] = inter ? ks[i] : z4;
        }
        const float4* vsrc = (const float4*)(Vbuf + (((b * 4 + g) * PPAD + ip0 * 54) << 6));
        float4* vt4s = (float4*)Vt;
        for (int i = t; i < VT_F4; i += 768) {
            unsigned pl = (unsigned)(i >> 4);
            unsigned lr = pl / 54u, col = pl - 54u * lr;
            unsigned grow = (unsigned)ip0 + lr;
            bool inter = (grow - 3u) < 48u && (col - 3u) < 48u;
            vt4s[i] = inter ? vsrc[i] : z4;
        }
    }

    const int rh  = (t >= 384) ? 1 : 0;
    const int tt  = t - rh * 384;
    const int ip  = ip0 + rh;
    const int pos = tt >> 3;
    const int sub = tt & 7;
    const int pidx = rh * 48 + pos;

    const float* qp = Qbuf + (((b * 4 + g) * 2304 + ip * 48 + pos) << 6);
    const float4 qlo = *(const float4*)(qp + 4 * sub);
    const float4 qhi = *(const float4*)(qp + 32 + 4 * sub);
    const ull ql0 = *(const ull*)&qlo.x, ql1 = *(const ull*)&qlo.z;
    const ull qh0 = *(const ull*)&qhi.x, qh1 = *(const ull*)&qhi.z;

    const bool useH = (SL < 4);
    const float* rp = useH ? (rpeh + SL * 224) : (rpew + (SL - 4) * 224);
    // ---- RPE via two batched transpose-reduces (14 SHFL total) ----
    {
        float P0[8], P1[8];
#pragma unroll
        for (int j = 0; j < 4; j++) {
            float4 rv = *(const float4*)(rp + j * 32 + 4 * sub);
            P0[j]     = dot4(qlo, rv);
            P0[4 + j] = dot4(qhi, rv);
        }
#pragma unroll
        for (int j = 0; j < 3; j++) {
            float4 rv = *(const float4*)(rp + (4 + j) * 32 + 4 * sub);
            P1[j]     = dot4(qlo, rv);
            P1[4 + j] = dot4(qhi, rv);
        }
        P1[3] = 0.f; P1[7] = 0.f;
        float r0 = treduce8(P0, sub);
        float r1 = treduce8(P1, sub);
        // P0: lanes 0..3 own Rlo[0..3]; lanes 4..7 own Rhi[0..3]
        if (sub < 4) rtab[pidx * 16 + sub] = r0;
        else         rtab[pidx * 16 + 8 + (sub - 4)] = r0;
        // P1: lanes 0..2 own Rlo[4..6]; lanes 4..6 own Rhi[4..6]
        if (sub < 3)               rtab[pidx * 16 + 4 + sub] = r1;
        else if (sub >= 4 && sub < 7) rtab[pidx * 16 + 8 + sub] = r1;
    }

    __syncthreads();

    float Radd[7];
#pragma unroll
    for (int i = 0; i < 7; i++) {
        int k = 8 * i + sub;
        int kc = (k > 48) ? 48 : k;
        int wA, wB;
        if (kc < 24)       { wA = 2 * kc;      wB = 2 * kc + 1; }
        else if (kc == 24) { wA = 48;          wB = 0; }
        else               { wA = 2 * kc - 49; wB = 2 * kc - 48; }
        int khA = wA / 7, kwA = wA - 7 * khA;
        int khB = wB / 7, kwB = wB - 7 * khB;
        int idxA = useH ? khA : kwA;
        int idxB = useH ? khB : kwB;
        Radd[i] = rtab[pidx * 16 + idxA] + rtab[pidx * 16 + 8 + idxB];
    }

    const int rsel = (pos >= 24) ? 1 : 0;
    const int j0 = 2 * pos - 48 * rsel;
    const int krow0 = 2 * rh + rsel;

    const float4* kt4 = (const float4*)Kt;
    const float4* kbase = kt4 + ((krow0 * 54 + j0) << 3) + sub;

    float Lreg[7];
#pragma unroll
    for (int c = 0; c < 7; c++) {
        float P[8];
#pragma unroll
        for (int kk = 0; kk < 8; kk++) {
            const int k = 8 * c + kk;
            const int kc = (k > 48) ? 48 : k;
            int wA, wB, rA, rB;
            if (kc < 24)       { wA = 2 * kc;      rA = 0; wB = 2 * kc + 1;  rB = 0; }
            else if (kc == 24) { wA = 48;          rA = 0; wB = 0;           rB = 1; }
            else               { wA = 2 * kc - 49; rA = 1; wB = 2 * kc - 48; rB = 1; }
            const int khA = wA / 7, kwA = wA % 7;
            const int khB = wB / 7, kwB = wB % 7;
            float4 va = kbase[(khA * 54 + rA + kwA) << 3];
            float4 vb = kbase[(khB * 54 + rB + kwB) << 3];
            ull aA = 0ull, aB = 0ull;
            fma2(aA, *(const ull*)&va.x, ql0);
            fma2(aA, *(const ull*)&va.z, ql1);
            fma2(aB, *(const ull*)&vb.x, qh0);
            fma2(aB, *(const ull*)&vb.z, qh1);
            ull s = add2(aA, aB);
            float2 sf = *(float2*)&s;
            P[kk] = sf.x + sf.y;
        }
        Lreg[c] = treduce8(P, sub) + Radd[c];
    }
    if (sub != 0) Lreg[6] = -1e30f;

    const int nk = (sub == 0) ? 7 : 6;
    float m = -1e30f;
#pragma unroll
    for (int i = 0; i < 7; i++)
        if (i < nk) m = fmaxf(m, Lreg[i]);
    m = max8(m);
    float ssum = 0.f;
#pragma unroll
    for (int i = 0; i < 7; i++)
        if (i < nk) { Lreg[i] = __expf(Lreg[i] - m); ssum += Lreg[i]; }
    ssum = red8(ssum);
    float inv = 1.0f / ssum;
#pragma unroll
    for (int i = 0; i < 7; i++) {
        int k = 8 * i + sub;
        if (k < 49) atts[pidx * ATT_STRIDE + k] = Lreg[i] * inv;
    }
    __syncwarp();

    // AV (f32x2), atts loaded as float4
    ull a0[2] = {0ull, 0ull}, a1[2] = {0ull, 0ull};
    const float4* vt4 = (const float4*)Vt;
#pragma unroll
    for (int kq = 0; kq < 13; kq++) {
        float4 a4 = *(const float4*)&atts[pidx * ATT_STRIDE + kq * 4];
        float aa[4] = {a4.x, a4.y, a4.z, a4.w};
#pragma unroll
        for (int j = 0; j < 4; j++) {
            const int k = kq * 4 + j;
            if (k < 49) {
                const int kh = k / 7, kw = k % 7;
                ull ad = dup2(aa[j]);
                const float4* vv = vt4 + ((((rh + kh) * 54 + pos + kw) << 4) + sub);
                float4 v0 = vv[0];
                float4 v1 = vv[8];
                fma2(a0[0], ad, *(ull*)&v0.x);
                fma2(a0[1], ad, *(ull*)&v0.z);
                fma2(a1[0], ad, *(ull*)&v1.x);
                fma2(a1[1], ad, *(ull*)&v1.z);
            }
        }
    }
    float4 acc0 = *(float4*)&a0[0];
    float4 acc1 = *(float4*)&a1[0];

    float* op = out + (b * 256 + g * 64) * NPOS + ip * 48 + pos;
    op[(4 * sub + 0) * NPOS] = acc0.x;
    op[(4 * sub + 1) * NPOS] = acc0.y;
    op[(4 * sub + 2) * NPOS] = acc0.z;
    op[(4 * sub + 3) * NPOS] = acc0.w;
    op[(32 + 4 * sub + 0) * NPOS] = acc1.x;
    op[(32 + 4 * sub + 1) * NPOS] = acc1.y;
    op[(32 + 4 * sub + 2) * NPOS] = acc1.z;
    op[(32 + 4 * sub + 3) * NPOS] = acc1.w;
}

// ---------------------------------------------------------------------------
extern "C" void kernel_launch(void* const* d_in, const int* in_sizes, int n_in,
                              void* d_out, int out_size) {
    const float* x  = (const float*)d_in[0];
    const float* w  = (const float*)d_in[1];
    const float* rh = (const float*)d_in[2];
    const float* rw = (const float*)d_in[3];
    float* out = (float*)d_out;

    cudaFuncSetAttribute(conv_mma, cudaFuncAttributeMaxDynamicSharedMemorySize, CONV_SMEM);
    dim3 gc(24, 6, 2);   // n=2304/96, o=768/128, b
    conv_mma<<<gc, 256, CONV_SMEM>>>(x, w);

    const int SMEM = (17280 + 27648 + 96 * ATT_STRIDE + 96 * 16) * 4;
    cudaFuncSetAttribute(attn_kernel, cudaFuncAttributeMaxDynamicSharedMemorySize, SMEM);
    dim3 ga(24, 4, 2);
    attn_kernel<<<ga, 768, SMEM>>>(rh, rw, out);
}